// round 15
// baseline (speedup 1.0000x reference)
#include <cuda_runtime.h>
#include <cuda_bf16.h>
#include <math.h>
#include <stdint.h>

#define BSZ   16
#define NTOT  8208
#define HD    768
#define NG    5
#define NM    96

// output offsets (flattened concat of the 8 reference outputs, float32)
#define OFF_GLOG 0
#define OFF_GPRB 656640
#define OFF_CLOG 1313280
#define OFF_ACC  1444608
#define OFF_NRM  1575936
#define OFF_GLBL 1575941
#define OFF_CLBL 1707269
#define OFF_CDST 1838597

__device__ __nv_bfloat16 g_W2h[128 * HD];
__device__ __nv_bfloat16 g_W2l[128 * HD];
__device__ float g_Cbg[BSZ * NG];
__device__ __align__(256) float g_SaaSam[10 * NTOT];   // SoA
__device__ __align__(256) float g_S[(NM) * NTOT];
__device__ unsigned g_rowmax_u[BSZ];
__device__ float g_cnt[NG];
__device__ float g_sum[NG];

__device__ __forceinline__ float wred(float v) {
    #pragma unroll
    for (int o = 16; o; o >>= 1) v += __shfl_down_sync(0xffffffffu, v, o);
    return v;
}
__device__ __forceinline__ unsigned fenc(float f) {
    unsigned b = __float_as_uint(f);
    return (b & 0x80000000u) ? ~b : (b | 0x80000000u);
}
__device__ __forceinline__ float fdec(unsigned u) {
    return (u & 0x80000000u) ? __uint_as_float(u ^ 0x80000000u)
                             : __uint_as_float(~u);
}

// ---------------------------------------------------------------------------
// mma.sync / ldmatrix / cp.async helpers (plain sm_80+)
// ---------------------------------------------------------------------------
__device__ __forceinline__ uint32_t smem_u32(const void* p) {
    uint32_t a;
    asm("{ .reg .u64 t; cvta.to.shared.u64 t, %1; cvt.u32.u64 %0, t; }"
        : "=r"(a) : "l"(p));
    return a;
}
__device__ __forceinline__ void mma16816(float* c, const uint32_t* a, const uint32_t* b) {
    asm volatile("mma.sync.aligned.m16n8k16.row.col.f32.bf16.bf16.f32 "
                 "{%0,%1,%2,%3}, {%4,%5,%6,%7}, {%8,%9}, {%0,%1,%2,%3};"
                 : "+f"(c[0]), "+f"(c[1]), "+f"(c[2]), "+f"(c[3])
                 : "r"(a[0]), "r"(a[1]), "r"(a[2]), "r"(a[3]),
                   "r"(b[0]), "r"(b[1]));
}
__device__ __forceinline__ void ldsm4(uint32_t* r, uint32_t addr) {
    asm volatile("ldmatrix.sync.aligned.m8n8.x4.shared.b16 {%0,%1,%2,%3}, [%4];"
                 : "=r"(r[0]), "=r"(r[1]), "=r"(r[2]), "=r"(r[3]) : "r"(addr));
}
__device__ __forceinline__ void cp16(uint32_t dst, const void* src) {
    size_t g;
    asm("cvta.to.global.u64 %0, %1;" : "=l"(g) : "l"(src));
    asm volatile("cp.async.ca.shared.global [%0], [%1], 16;"
                 :: "r"(dst), "l"(g) : "memory");
}

__device__ __forceinline__ void split2(float v0, float v1, uint32_t& h, uint32_t& l) {
    asm("cvt.rn.bf16x2.f32 %0, %1, %2;" : "=r"(h) : "f"(v1), "f"(v0));
    float h0 = __uint_as_float(h << 16);
    float h1 = __uint_as_float(h & 0xffff0000u);
    float l0 = v0 - h0, l1 = v1 - h1;
    asm("cvt.rn.bf16x2.f32 %0, %1, %2;" : "=r"(l) : "f"(l1), "f"(l0));
}
__device__ __forceinline__ void split8(const float* v, uint4& hi, uint4& lo) {
    uint32_t hs[4], ls[4];
    #pragma unroll
    for (int p = 0; p < 4; p++) split2(v[2 * p], v[2 * p + 1], hs[p], ls[p]);
    hi = make_uint4(hs[0], hs[1], hs[2], hs[3]);
    lo = make_uint4(ls[0], ls[1], ls[2], ls[3]);
}

// ---------------------------------------------------------------------------
// K1: merged prep — blocks [0,384): W2 build; blocks [384,394): Cbg
// ---------------------------------------------------------------------------
__global__ void prep_kernel(const float* __restrict__ q,
                            const float* __restrict__ mu,
                            const float* __restrict__ lgs,
                            const float* __restrict__ pi) {
    if (blockIdx.x < 384) {
        int i = blockIdx.x * 256 + threadIdx.x;
        if (blockIdx.x == 0 && threadIdx.x < 32) {
            if (threadIdx.x < NG)  { g_cnt[threadIdx.x] = 0.f; g_sum[threadIdx.x] = 0.f; }
            if (threadIdx.x < BSZ) g_rowmax_u[threadIdx.x] = 0u;
        }
        if (i >= 128 * HD) return;
        int m = i / HD, h = i - m * HD;
        float w = 0.f;
        if (m < BSZ) w = q[m * HD + h];
        else if (m < NM) {
            int bg = m - BSZ;
            int b = bg / NG, g = bg - b * NG;
            w = q[b * HD + h] * expf(-lgs[g * HD + h]);
        } else if (m < NM + NG) {
            int g = m - NM;
            w = mu[g * HD + h] * expf(-lgs[g * HD + h]);
        }
        __nv_bfloat16 hb = __float2bfloat16(w);
        float lo = w - __bfloat162float(hb);
        g_W2h[i] = hb;
        g_W2l[i] = __float2bfloat16(lo);
    } else {
        int job = (blockIdx.x - 384) * 8 + (threadIdx.x >> 5);
        int lane = threadIdx.x & 31;
        if (job >= BSZ * NG) return;
        int b = job / NG, g = job - b * NG;

        float a1 = 0.f, a2 = 0.f;
        for (int h = lane; h < HD; h += 32) {
            float lv = lgs[g * HD + h];
            float iv = expf(-lv);
            float m_ = mu[g * HD + h];
            float mv = m_ * iv;
            float qv = q[b * HD + h];
            a1 += lv + qv * qv * iv + m_ * mv;
            a2 += qv * mv;
        }
        a1 = wred(a1); a2 = wred(a2);
        if (lane == 0) {
            float m = pi[0];
            #pragma unroll
            for (int i = 1; i < NG; i++) m = fmaxf(m, pi[i]);
            float s = 0.f;
            #pragma unroll
            for (int i = 0; i < NG; i++) s += expf(pi[i] - m);
            float lse = m + logf(s);
            const float LG2PID = 768.0f * 1.8378770351409912f;
            g_Cbg[job] = (pi[g] - lse) - 0.5f * (LG2PID + a1) + a2;
        }
    }
}

// ===========================================================================
// K2: HMMA bf16x3 fused GEMM (identical to R14, passing)
// ===========================================================================
#define NSTG  12
#define A_HI  0
#define A_LO  36864
#define B_HI  73728
#define B_LO  92160
#define SQ_HI 110592
#define SQ_LO 129024
#define IV_HI 147456
#define IV_LO 155216
#define ZROW  162976
#define SMTOT 162992

__global__ __launch_bounds__(512, 1) void gemm_mma_kernel(const float* __restrict__ sk,
                                                          const float* __restrict__ qu,
                                                          const float* __restrict__ lgs) {
    extern __shared__ __align__(1024) unsigned char smem[];
    const uint32_t sb = smem_u32(smem);
    const int tid = threadIdx.x;
    const int lane = tid & 31;
    const int warp = tid >> 5;
    const int mi = warp >> 2;
    const int ni = warp & 3;
    const int n0 = blockIdx.x * 64;

    for (int i = tid; i < 5 * 384; i += 512) {
        int r = i / 384, kp = i - r * 384;
        float2 v2 = *(const float2*)(lgs + r * HD + kp * 2);
        uint32_t h, l;
        split2(expf(-v2.x), expf(-v2.y), h, l);
        *(uint32_t*)(smem + IV_HI + r * 1552 + kp * 4) = h;
        *(uint32_t*)(smem + IV_LO + r * 1552 + kp * 4) = l;
    }
    if (tid < 4) *(uint32_t*)(smem + ZROW + tid * 4) = 0u;

    const __nv_bfloat16* aps[4];
    uint32_t apd[4];
    #pragma unroll
    for (int i = 0; i < 4; i++) {
        int j = tid + i * 512;
        int part = j >> 10;
        int rem = j & 1023;
        int row = rem >> 3, ch = rem & 7;
        aps[i] = (part ? g_W2l : g_W2h) + row * HD + ch * 8;
        apd[i] = sb + (part ? A_LO : A_HI) + row * 144 + ch * 16;
    }

    const int col = tid >> 3;
    const int kq8 = (tid & 7) * 8;
    const int n   = n0 + col;
    const bool okB = (n < NTOT);
    const float* bsrc = okB ? ((n < BSZ) ? sk + n * HD : qu + (size_t)(n - BSZ) * HD)
                            : sk;
    const uint32_t bOff = col * 144 + kq8 * 2;

    const uint32_t aB = sb + A_HI + (mi * 32 + (lane & 15)) * 144 + (lane >> 4) * 16;
    const uint32_t bBm = sb + B_HI + (ni * 16 + (lane >> 4) * 8 + (lane & 7)) * 144
                         + ((lane >> 3) & 1) * 16;
    const int rr = lane & 15;
    const uint32_t ivH = (rr < 5) ? sb + IV_HI + rr * 1552 + (lane >> 4) * 16 : sb + ZROW;
    const uint32_t ivL = (rr < 5) ? sb + IV_LO + rr * 1552 + (lane >> 4) * 16 : sb + ZROW;
    const int ivs = (rr < 5) ? 32 : 0;
    const int tt = ni * 2 + mi;
    const uint32_t sqBm = sb + SQ_HI + ((lane >> 4) ? 18432u : 0u)
                          + (tt * 8 + (lane & 7)) * 144 + ((lane >> 3) & 1) * 16;

    float acc[2][2][4];
    #pragma unroll
    for (int a = 0; a < 2; a++)
        #pragma unroll
        for (int b = 0; b < 2; b++)
            #pragma unroll
            for (int c = 0; c < 4; c++) acc[a][b][c] = 0.f;
    float d2[4] = {0.f, 0.f, 0.f, 0.f};

    const float4 z4 = make_float4(0.f, 0.f, 0.f, 0.f);

    {
        float4 b0 = okB ? *(const float4*)(bsrc + kq8)     : z4;
        float4 b1 = okB ? *(const float4*)(bsrc + kq8 + 4) : z4;
        float v[8] = {b0.x, b0.y, b0.z, b0.w, b1.x, b1.y, b1.z, b1.w};
        uint4 hi, lo;
        split8(v, hi, lo);
        *(uint4*)(smem + B_HI + bOff) = hi;
        *(uint4*)(smem + B_LO + bOff) = lo;
        #pragma unroll
        for (int i = 0; i < 8; i++) v[i] *= v[i];
        split8(v, hi, lo);
        *(uint4*)(smem + SQ_HI + bOff) = hi;
        *(uint4*)(smem + SQ_LO + bOff) = lo;
    }
    #pragma unroll
    for (int i = 0; i < 4; i++) cp16(apd[i], aps[i]);
    asm volatile("cp.async.commit_group;" ::: "memory");

    float4 pb0 = okB ? *(const float4*)(bsrc + 64 + kq8)     : z4;
    float4 pb1 = okB ? *(const float4*)(bsrc + 64 + kq8 + 4) : z4;

    for (int s = 0; s < NSTG; s++) {
        const int buf = s & 1;
        asm volatile("cp.async.wait_group 0;" ::: "memory");
        __syncthreads();

        if (s + 1 < NSTG) {
            const int nb = buf ^ 1;
            #pragma unroll
            for (int i = 0; i < 4; i++)
                cp16(apd[i] + nb * 18432, aps[i] + (s + 1) * 64);
            asm volatile("cp.async.commit_group;" ::: "memory");
            {
                float v[8] = {pb0.x, pb0.y, pb0.z, pb0.w, pb1.x, pb1.y, pb1.z, pb1.w};
                uint4 hi, lo;
                split8(v, hi, lo);
                uint32_t off = nb * 9216 + bOff;
                *(uint4*)(smem + B_HI + off) = hi;
                *(uint4*)(smem + B_LO + off) = lo;
                #pragma unroll
                for (int i = 0; i < 8; i++) v[i] *= v[i];
                split8(v, hi, lo);
                *(uint4*)(smem + SQ_HI + off) = hi;
                *(uint4*)(smem + SQ_LO + off) = lo;
            }
            if (s + 2 < NSTG) {
                pb0 = okB ? *(const float4*)(bsrc + (s + 2) * 64 + kq8)     : z4;
                pb1 = okB ? *(const float4*)(bsrc + (s + 2) * 64 + kq8 + 4) : z4;
            }
        }

        const uint32_t aO = buf * 18432u;
        const uint32_t bO = buf * 9216u;

        uint32_t ah[2][2][4], al[2][2][4], bh[2][4], bl[2][4];
        #pragma unroll
        for (int mt = 0; mt < 2; mt++) {
            ldsm4(ah[0][mt], aB + aO + mt * 2304);
            ldsm4(al[0][mt], aB + aO + mt * 2304 + 36864);
        }
        ldsm4(bh[0], bBm + bO);
        ldsm4(bl[0], bBm + bO + 18432);

        #pragma unroll
        for (int su = 0; su < 4; su++) {
            const int cur = su & 1, nxt = cur ^ 1;
            if (su < 3) {
                const uint32_t ko = (su + 1) * 32;
                #pragma unroll
                for (int mt = 0; mt < 2; mt++) {
                    ldsm4(ah[nxt][mt], aB + aO + mt * 2304 + ko);
                    ldsm4(al[nxt][mt], aB + aO + mt * 2304 + ko + 36864);
                }
                ldsm4(bh[nxt], bBm + bO + ko);
                ldsm4(bl[nxt], bBm + bO + ko + 18432);
            }
            #pragma unroll
            for (int mt = 0; mt < 2; mt++)
                #pragma unroll
                for (int nt = 0; nt < 2; nt++) {
                    mma16816(acc[mt][nt], ah[cur][mt], &bh[cur][nt * 2]);
                    mma16816(acc[mt][nt], ah[cur][mt], &bl[cur][nt * 2]);
                    mma16816(acc[mt][nt], al[cur][mt], &bh[cur][nt * 2]);
                }
            if (mi < 2) {
                const int t16 = s * 4 + su;
                uint32_t ivh[4], ivl[4], sv[4];
                ldsm4(ivh, ivH + t16 * ivs);
                ldsm4(ivl, ivL + t16 * ivs);
                ldsm4(sv, sqBm + bO + su * 32);
                mma16816(d2, ivh, &sv[0]);
                mma16816(d2, ivh, &sv[2]);
                mma16816(d2, ivl, &sv[0]);
            }
        }
    }

    // ---- epilogue ----
    const int r0  = lane >> 2;
    const int c0l = (lane & 3) * 2;
    float mx0 = -3.4e38f, mx1 = -3.4e38f;

    #pragma unroll
    for (int mt = 0; mt < 2; mt++) {
        const int mb = mi * 32 + mt * 16;
        #pragma unroll
        for (int nt = 0; nt < 2; nt++) {
            const int cg = n0 + ni * 16 + nt * 8 + c0l;
            if (cg >= NTOT) continue;
            const float* c = acc[mt][nt];
            const int m0 = mb + r0, m1 = m0 + 8;
            if (m0 < NM) {
                *(float2*)&g_S[(size_t)m0 * NTOT + cg] = make_float2(c[0], c[1]);
                if (m0 < BSZ) mx0 = fmaxf(mx0, fmaxf(c[0], c[1]));
            } else if (m0 < NM + NG) {
                *(float2*)&g_SaaSam[(size_t)(5 + m0 - NM) * NTOT + cg] =
                    make_float2(c[0], c[1]);
            }
            if (m1 < NM) {
                *(float2*)&g_S[(size_t)m1 * NTOT + cg] = make_float2(c[2], c[3]);
                if (m1 < BSZ) mx1 = fmaxf(mx1, fmaxf(c[2], c[3]));
            } else if (m1 < NM + NG) {
                *(float2*)&g_SaaSam[(size_t)(5 + m1 - NM) * NTOT + cg] =
                    make_float2(c[2], c[3]);
            }
        }
    }
    if (mi == 0) {
        if (r0 < BSZ)     atomicMax(&g_rowmax_u[r0], fenc(mx0));
        if (r0 + 8 < BSZ) atomicMax(&g_rowmax_u[r0 + 8], fenc(mx1));
    }
    if (mi < 2 && r0 < NG) {
        const int cg = n0 + tt * 8 + c0l;
        if (cg < NTOT)
            *(float2*)&g_SaaSam[(size_t)r0 * NTOT + cg] = make_float2(d2[0], d2[1]);
    }
}

// ---------------------------------------------------------------------------
// K3: fused epilogue, 2 cells (b, n) and (b+8, n) per thread — ss/rm loads
//     shared across the pair; both halves keep contiguous staged write-out.
// ---------------------------------------------------------------------------
#define NPAIR (8 * NTOT)       // 65664
__global__ __launch_bounds__(256, 2) void epi_kernel(const float* __restrict__ rank_mean,
                                                     float* __restrict__ out) {
    __shared__ float s_cnt[NG], s_sum[NG];
    __shared__ __align__(16) float stG[2560];
    __shared__ __align__(16) float stP[2560];
    const int tid = threadIdx.x;
    if (tid < NG) { s_cnt[tid] = 0.f; s_sum[tid] = 0.f; }
    __syncthreads();

    const int j = blockIdx.x * 256 + tid;
    const bool valid = (j < NPAIR);
    const int jj = valid ? j : (NPAIR - 1);
    const int b0 = jj / NTOT;
    const int n  = jj - b0 * NTOT;

    // shared-across-pair loads
    float ss[10];
    #pragma unroll
    for (int i = 0; i < 10; i++)
        ss[i] = g_SaaSam[(size_t)i * NTOT + n];
    float rm[NG];
    #pragma unroll
    for (int g = 0; g < NG; g++) rm[g] = rank_mean[g];

    #pragma unroll
    for (int half = 0; half < 2; half++) {
        const int b = b0 + half * 8;
        const float sim = g_S[(size_t)b * NTOT + n];
        float lg[NG], ev[NG];
        #pragma unroll
        for (int g = 0; g < NG; g++)
            lg[g] = g_Cbg[b * NG + g] + g_S[(size_t)(BSZ + b * NG + g) * NTOT + n]
                    - 0.5f * ss[g] - ss[5 + g];
        float m = lg[0]; int bi = 0;
        #pragma unroll
        for (int g = 1; g < NG; g++) if (lg[g] > m) { m = lg[g]; bi = g; }
        float sum = 0.f;
        #pragma unroll
        for (int g = 0; g < NG; g++) {
            float ln = lg[g] - m;
            stG[half * 1280 + tid * 5 + g] = ln;
            float e = __expf(ln);
            ev[g] = e; sum += e;
        }
        float isum = 1.f / sum;
        #pragma unroll
        for (int g = 0; g < NG; g++)
            stP[half * 1280 + tid * 5 + g] = ev[g] * isum;

        if (valid) {
            float bd = fabsf(sim - rm[0]); int cp = 0;
            #pragma unroll
            for (int g = 1; g < NG; g++) {
                float d = fabsf(sim - rm[g]);
                if (d < bd) { bd = d; cp = g; }
            }
            int cd = (int)floorf((sim + 1.0f) / 2.0f * 5.0f);
            bool golden = (n < BSZ) && (n == ((b + 8) & 15));
            bool eye    = (n == b);
            const size_t idx = (size_t)b * NTOT + n;
            out[OFF_CLOG + idx] = sim - fdec(g_rowmax_u[b]);
            out[OFF_ACC  + idx] = eye ? 0.f : sim;
            out[OFF_GLBL + idx] = (float)((eye || golden) ? (NG - 1) : cp);
            out[OFF_CLBL + idx] = (float)(golden ? (NG - 1) : bi);
            out[OFF_CDST + idx] = (float)cd;
            atomicAdd(&s_cnt[bi], 1.f);
            atomicAdd(&s_sum[bi], sim);
        }
    }
    __syncthreads();

    // coalesced copy-out; per-block valid cells (full 256, or 128 in the tail)
    {
        const int vcells = min(256, NPAIR - blockIdx.x * 256);
        const int vq = (vcells * 5) / 4;       // 320 or 160
        const float4* sg = (const float4*)stG;
        const float4* sp = (const float4*)stP;
        const size_t base0 = (size_t)blockIdx.x * 1280;
        const size_t base1 = base0 + (size_t)8 * NTOT * 5;
        #pragma unroll
        for (int i = 0; i < 2; i++) {
            int e = tid + i * 256;
            if (e < 320 && e < vq) {
                ((float4*)(out + OFF_GLOG + base0))[e] = sg[e];
                ((float4*)(out + OFF_GPRB + base0))[e] = sp[e];
                ((float4*)(out + OFF_GLOG + base1))[e] = sg[320 + e];
                ((float4*)(out + OFF_GPRB + base1))[e] = sp[320 + e];
            }
        }
    }
    if (tid < NG) {
        atomicAdd(&g_cnt[tid], s_cnt[tid]);
        atomicAdd(&g_sum[tid], s_sum[tid]);
    }
}

// ---------------------------------------------------------------------------
// K4: rank-mean EMA finalize
// ---------------------------------------------------------------------------
__global__ void finish_kernel(const float* __restrict__ rank_mean,
                              float* __restrict__ out) {
    int g = threadIdx.x;
    if (g < NG) {
        float c = g_cnt[g], s = g_sum[g];
        float cur = s / (c + 1e-12f);
        float upd = (c != 0.f) ? 1.f : 0.f;
        out[OFF_NRM + g] = (1.f - upd * 0.1f) * rank_mean[g] + upd * 0.1f * cur;
    }
}

// ---------------------------------------------------------------------------
extern "C" void kernel_launch(void* const* d_in, const int* in_sizes, int n_in,
                              void* d_out, int out_size) {
    const float* sent_q    = (const float*)d_in[0];
    const float* sent_k    = (const float*)d_in[1];
    const float* queue     = (const float*)d_in[2];
    const float* mu        = (const float*)d_in[3];
    const float* lg_sigma2 = (const float*)d_in[4];
    const float* pi        = (const float*)d_in[5];
    const float* rank_mean = (const float*)d_in[6];
    float* out = (float*)d_out;

    cudaFuncSetAttribute(gemm_mma_kernel,
                         cudaFuncAttributeMaxDynamicSharedMemorySize, SMTOT);

    prep_kernel<<<394, 256>>>(sent_q, mu, lg_sigma2, pi);
    gemm_mma_kernel<<<(NTOT + 63) / 64, 512, SMTOT>>>(sent_k, queue, lg_sigma2);
    epi_kernel<<<(NPAIR + 255) / 256, 256>>>(rank_mean, out);
    finish_kernel<<<1, 32>>>(rank_mean, out);
}

// round 16
// speedup vs baseline: 1.3469x; 1.3469x over previous
#include <cuda_runtime.h>
#include <cuda_bf16.h>
#include <math.h>
#include <stdint.h>

#define BSZ   16
#define NTOT  8208
#define HD    768
#define NG    5
#define NM    96

// output offsets (flattened concat of the 8 reference outputs, float32)
#define OFF_GLOG 0
#define OFF_GPRB 656640
#define OFF_CLOG 1313280
#define OFF_ACC  1444608
#define OFF_NRM  1575936
#define OFF_GLBL 1575941
#define OFF_CLBL 1707269
#define OFF_CDST 1838597

__device__ __nv_bfloat16 g_W2h[128 * HD];
__device__ __nv_bfloat16 g_W2l[128 * HD];
__device__ float g_Cbg[BSZ * NG];
__device__ __align__(256) float g_SaaSam[10 * NTOT];   // SoA
__device__ __align__(256) float g_S[(NM) * NTOT];
__device__ unsigned g_rowmax_u[BSZ];
__device__ float g_cnt[NG];
__device__ float g_sum[NG];

__device__ __forceinline__ float wred(float v) {
    #pragma unroll
    for (int o = 16; o; o >>= 1) v += __shfl_down_sync(0xffffffffu, v, o);
    return v;
}
__device__ __forceinline__ unsigned fenc(float f) {
    unsigned b = __float_as_uint(f);
    return (b & 0x80000000u) ? ~b : (b | 0x80000000u);
}
__device__ __forceinline__ float fdec(unsigned u) {
    return (u & 0x80000000u) ? __uint_as_float(u ^ 0x80000000u)
                             : __uint_as_float(~u);
}

// ---------------------------------------------------------------------------
// mma.sync / ldmatrix / cp.async helpers (plain sm_80+)
// ---------------------------------------------------------------------------
__device__ __forceinline__ uint32_t smem_u32(const void* p) {
    uint32_t a;
    asm("{ .reg .u64 t; cvta.to.shared.u64 t, %1; cvt.u32.u64 %0, t; }"
        : "=r"(a) : "l"(p));
    return a;
}
__device__ __forceinline__ void mma16816(float* c, const uint32_t* a, const uint32_t* b) {
    asm volatile("mma.sync.aligned.m16n8k16.row.col.f32.bf16.bf16.f32 "
                 "{%0,%1,%2,%3}, {%4,%5,%6,%7}, {%8,%9}, {%0,%1,%2,%3};"
                 : "+f"(c[0]), "+f"(c[1]), "+f"(c[2]), "+f"(c[3])
                 : "r"(a[0]), "r"(a[1]), "r"(a[2]), "r"(a[3]),
                   "r"(b[0]), "r"(b[1]));
}
__device__ __forceinline__ void ldsm4(uint32_t* r, uint32_t addr) {
    asm volatile("ldmatrix.sync.aligned.m8n8.x4.shared.b16 {%0,%1,%2,%3}, [%4];"
                 : "=r"(r[0]), "=r"(r[1]), "=r"(r[2]), "=r"(r[3]) : "r"(addr));
}
__device__ __forceinline__ void cp16(uint32_t dst, const void* src) {
    size_t g;
    asm("cvta.to.global.u64 %0, %1;" : "=l"(g) : "l"(src));
    asm volatile("cp.async.ca.shared.global [%0], [%1], 16;"
                 :: "r"(dst), "l"(g) : "memory");
}

__device__ __forceinline__ void split2(float v0, float v1, uint32_t& h, uint32_t& l) {
    asm("cvt.rn.bf16x2.f32 %0, %1, %2;" : "=r"(h) : "f"(v1), "f"(v0));
    float h0 = __uint_as_float(h << 16);
    float h1 = __uint_as_float(h & 0xffff0000u);
    float l0 = v0 - h0, l1 = v1 - h1;
    asm("cvt.rn.bf16x2.f32 %0, %1, %2;" : "=r"(l) : "f"(l1), "f"(l0));
}
__device__ __forceinline__ void split8(const float* v, uint4& hi, uint4& lo) {
    uint32_t hs[4], ls[4];
    #pragma unroll
    for (int p = 0; p < 4; p++) split2(v[2 * p], v[2 * p + 1], hs[p], ls[p]);
    hi = make_uint4(hs[0], hs[1], hs[2], hs[3]);
    lo = make_uint4(ls[0], ls[1], ls[2], ls[3]);
}

// ---------------------------------------------------------------------------
// K1: W2 = [q(16); q*inv_g(80); mu*inv(5); zeros] split hi/lo; init accums
// ---------------------------------------------------------------------------
__global__ void w2_kernel(const float* __restrict__ q,
                          const float* __restrict__ mu,
                          const float* __restrict__ lgs) {
    int i = blockIdx.x * 256 + threadIdx.x;
    if (blockIdx.x == 0 && threadIdx.x < 32) {
        if (threadIdx.x < NG)  { g_cnt[threadIdx.x] = 0.f; g_sum[threadIdx.x] = 0.f; }
        if (threadIdx.x < BSZ) g_rowmax_u[threadIdx.x] = 0u;
    }
    if (i >= 128 * HD) return;
    int m = i / HD, h = i - m * HD;
    float w = 0.f;
    if (m < BSZ) w = q[m * HD + h];
    else if (m < NM) {
        int bg = m - BSZ;
        int b = bg / NG, g = bg - b * NG;
        w = q[b * HD + h] * expf(-lgs[g * HD + h]);
    } else if (m < NM + NG) {
        int g = m - NM;
        w = mu[g * HD + h] * expf(-lgs[g * HD + h]);
    }
    __nv_bfloat16 hb = __float2bfloat16(w);
    float lo = w - __bfloat162float(hb);
    g_W2h[i] = hb;
    g_W2l[i] = __float2bfloat16(lo);
}

// ---------------------------------------------------------------------------
// K2: per-(b,g) constants Cbg
// ---------------------------------------------------------------------------
__global__ void cbg_kernel(const float* __restrict__ q,
                           const float* __restrict__ mu,
                           const float* __restrict__ lgs,
                           const float* __restrict__ pi) {
    int job = blockIdx.x * 8 + (threadIdx.x >> 5);
    int lane = threadIdx.x & 31;
    if (job >= BSZ * NG) return;
    int b = job / NG, g = job - b * NG;

    float a1 = 0.f, a2 = 0.f;
    for (int h = lane; h < HD; h += 32) {
        float lv = lgs[g * HD + h];
        float iv = expf(-lv);
        float m_ = mu[g * HD + h];
        float mv = m_ * iv;
        float qv = q[b * HD + h];
        a1 += lv + qv * qv * iv + m_ * mv;
        a2 += qv * mv;
    }
    a1 = wred(a1); a2 = wred(a2);
    if (lane == 0) {
        float m = pi[0];
        #pragma unroll
        for (int i = 1; i < NG; i++) m = fmaxf(m, pi[i]);
        float s = 0.f;
        #pragma unroll
        for (int i = 0; i < NG; i++) s += expf(pi[i] - m);
        float lse = m + logf(s);
        const float LG2PID = 768.0f * 1.8378770351409912f;
        g_Cbg[job] = (pi[g] - lse) - 0.5f * (LG2PID + a1) + a2;
    }
}

// ===========================================================================
// K3: HMMA bf16x3 fused GEMM (identical to R14, passing)
// ===========================================================================
#define NSTG  12
#define A_HI  0
#define A_LO  36864
#define B_HI  73728
#define B_LO  92160
#define SQ_HI 110592
#define SQ_LO 129024
#define IV_HI 147456
#define IV_LO 155216
#define ZROW  162976
#define SMTOT 162992

__global__ __launch_bounds__(512, 1) void gemm_mma_kernel(const float* __restrict__ sk,
                                                          const float* __restrict__ qu,
                                                          const float* __restrict__ lgs) {
    extern __shared__ __align__(1024) unsigned char smem[];
    const uint32_t sb = smem_u32(smem);
    const int tid = threadIdx.x;
    const int lane = tid & 31;
    const int warp = tid >> 5;
    const int mi = warp >> 2;
    const int ni = warp & 3;
    const int n0 = blockIdx.x * 64;

    for (int i = tid; i < 5 * 384; i += 512) {
        int r = i / 384, kp = i - r * 384;
        float2 v2 = *(const float2*)(lgs + r * HD + kp * 2);
        uint32_t h, l;
        split2(expf(-v2.x), expf(-v2.y), h, l);
        *(uint32_t*)(smem + IV_HI + r * 1552 + kp * 4) = h;
        *(uint32_t*)(smem + IV_LO + r * 1552 + kp * 4) = l;
    }
    if (tid < 4) *(uint32_t*)(smem + ZROW + tid * 4) = 0u;

    const __nv_bfloat16* aps[4];
    uint32_t apd[4];
    #pragma unroll
    for (int i = 0; i < 4; i++) {
        int j = tid + i * 512;
        int part = j >> 10;
        int rem = j & 1023;
        int row = rem >> 3, ch = rem & 7;
        aps[i] = (part ? g_W2l : g_W2h) + row * HD + ch * 8;
        apd[i] = sb + (part ? A_LO : A_HI) + row * 144 + ch * 16;
    }

    const int col = tid >> 3;
    const int kq8 = (tid & 7) * 8;
    const int n   = n0 + col;
    const bool okB = (n < NTOT);
    const float* bsrc = okB ? ((n < BSZ) ? sk + n * HD : qu + (size_t)(n - BSZ) * HD)
                            : sk;
    const uint32_t bOff = col * 144 + kq8 * 2;

    const uint32_t aB = sb + A_HI + (mi * 32 + (lane & 15)) * 144 + (lane >> 4) * 16;
    const uint32_t bBm = sb + B_HI + (ni * 16 + (lane >> 4) * 8 + (lane & 7)) * 144
                         + ((lane >> 3) & 1) * 16;
    const int rr = lane & 15;
    const uint32_t ivH = (rr < 5) ? sb + IV_HI + rr * 1552 + (lane >> 4) * 16 : sb + ZROW;
    const uint32_t ivL = (rr < 5) ? sb + IV_LO + rr * 1552 + (lane >> 4) * 16 : sb + ZROW;
    const int ivs = (rr < 5) ? 32 : 0;
    const int tt = ni * 2 + mi;
    const uint32_t sqBm = sb + SQ_HI + ((lane >> 4) ? 18432u : 0u)
                          + (tt * 8 + (lane & 7)) * 144 + ((lane >> 3) & 1) * 16;

    float acc[2][2][4];
    #pragma unroll
    for (int a = 0; a < 2; a++)
        #pragma unroll
        for (int b = 0; b < 2; b++)
            #pragma unroll
            for (int c = 0; c < 4; c++) acc[a][b][c] = 0.f;
    float d2[4] = {0.f, 0.f, 0.f, 0.f};

    const float4 z4 = make_float4(0.f, 0.f, 0.f, 0.f);

    {
        float4 b0 = okB ? *(const float4*)(bsrc + kq8)     : z4;
        float4 b1 = okB ? *(const float4*)(bsrc + kq8 + 4) : z4;
        float v[8] = {b0.x, b0.y, b0.z, b0.w, b1.x, b1.y, b1.z, b1.w};
        uint4 hi, lo;
        split8(v, hi, lo);
        *(uint4*)(smem + B_HI + bOff) = hi;
        *(uint4*)(smem + B_LO + bOff) = lo;
        #pragma unroll
        for (int i = 0; i < 8; i++) v[i] *= v[i];
        split8(v, hi, lo);
        *(uint4*)(smem + SQ_HI + bOff) = hi;
        *(uint4*)(smem + SQ_LO + bOff) = lo;
    }
    #pragma unroll
    for (int i = 0; i < 4; i++) cp16(apd[i], aps[i]);
    asm volatile("cp.async.commit_group;" ::: "memory");

    float4 pb0 = okB ? *(const float4*)(bsrc + 64 + kq8)     : z4;
    float4 pb1 = okB ? *(const float4*)(bsrc + 64 + kq8 + 4) : z4;

    for (int s = 0; s < NSTG; s++) {
        const int buf = s & 1;
        asm volatile("cp.async.wait_group 0;" ::: "memory");
        __syncthreads();

        if (s + 1 < NSTG) {
            const int nb = buf ^ 1;
            #pragma unroll
            for (int i = 0; i < 4; i++)
                cp16(apd[i] + nb * 18432, aps[i] + (s + 1) * 64);
            asm volatile("cp.async.commit_group;" ::: "memory");
            {
                float v[8] = {pb0.x, pb0.y, pb0.z, pb0.w, pb1.x, pb1.y, pb1.z, pb1.w};
                uint4 hi, lo;
                split8(v, hi, lo);
                uint32_t off = nb * 9216 + bOff;
                *(uint4*)(smem + B_HI + off) = hi;
                *(uint4*)(smem + B_LO + off) = lo;
                #pragma unroll
                for (int i = 0; i < 8; i++) v[i] *= v[i];
                split8(v, hi, lo);
                *(uint4*)(smem + SQ_HI + off) = hi;
                *(uint4*)(smem + SQ_LO + off) = lo;
            }
            if (s + 2 < NSTG) {
                pb0 = okB ? *(const float4*)(bsrc + (s + 2) * 64 + kq8)     : z4;
                pb1 = okB ? *(const float4*)(bsrc + (s + 2) * 64 + kq8 + 4) : z4;
            }
        }

        const uint32_t aO = buf * 18432u;
        const uint32_t bO = buf * 9216u;

        uint32_t ah[2][2][4], al[2][2][4], bh[2][4], bl[2][4];
        #pragma unroll
        for (int mt = 0; mt < 2; mt++) {
            ldsm4(ah[0][mt], aB + aO + mt * 2304);
            ldsm4(al[0][mt], aB + aO + mt * 2304 + 36864);
        }
        ldsm4(bh[0], bBm + bO);
        ldsm4(bl[0], bBm + bO + 18432);

        #pragma unroll
        for (int su = 0; su < 4; su++) {
            const int cur = su & 1, nxt = cur ^ 1;
            if (su < 3) {
                const uint32_t ko = (su + 1) * 32;
                #pragma unroll
                for (int mt = 0; mt < 2; mt++) {
                    ldsm4(ah[nxt][mt], aB + aO + mt * 2304 + ko);
                    ldsm4(al[nxt][mt], aB + aO + mt * 2304 + ko + 36864);
                }
                ldsm4(bh[nxt], bBm + bO + ko);
                ldsm4(bl[nxt], bBm + bO + ko + 18432);
            }
            #pragma unroll
            for (int mt = 0; mt < 2; mt++)
                #pragma unroll
                for (int nt = 0; nt < 2; nt++) {
                    mma16816(acc[mt][nt], ah[cur][mt], &bh[cur][nt * 2]);
                    mma16816(acc[mt][nt], ah[cur][mt], &bl[cur][nt * 2]);
                    mma16816(acc[mt][nt], al[cur][mt], &bh[cur][nt * 2]);
                }
            if (mi < 2) {
                const int t16 = s * 4 + su;
                uint32_t ivh[4], ivl[4], sv[4];
                ldsm4(ivh, ivH + t16 * ivs);
                ldsm4(ivl, ivL + t16 * ivs);
                ldsm4(sv, sqBm + bO + su * 32);
                mma16816(d2, ivh, &sv[0]);
                mma16816(d2, ivh, &sv[2]);
                mma16816(d2, ivl, &sv[0]);
            }
        }
    }

    // ---- epilogue ----
    const int r0  = lane >> 2;
    const int c0l = (lane & 3) * 2;
    float mx0 = -3.4e38f, mx1 = -3.4e38f;

    #pragma unroll
    for (int mt = 0; mt < 2; mt++) {
        const int mb = mi * 32 + mt * 16;
        #pragma unroll
        for (int nt = 0; nt < 2; nt++) {
            const int cg = n0 + ni * 16 + nt * 8 + c0l;
            if (cg >= NTOT) continue;
            const float* c = acc[mt][nt];
            const int m0 = mb + r0, m1 = m0 + 8;
            if (m0 < NM) {
                *(float2*)&g_S[(size_t)m0 * NTOT + cg] = make_float2(c[0], c[1]);
                if (m0 < BSZ) mx0 = fmaxf(mx0, fmaxf(c[0], c[1]));
            } else if (m0 < NM + NG) {
                *(float2*)&g_SaaSam[(size_t)(5 + m0 - NM) * NTOT + cg] =
                    make_float2(c[0], c[1]);
            }
            if (m1 < NM) {
                *(float2*)&g_S[(size_t)m1 * NTOT + cg] = make_float2(c[2], c[3]);
                if (m1 < BSZ) mx1 = fmaxf(mx1, fmaxf(c[2], c[3]));
            } else if (m1 < NM + NG) {
                *(float2*)&g_SaaSam[(size_t)(5 + m1 - NM) * NTOT + cg] =
                    make_float2(c[2], c[3]);
            }
        }
    }
    if (mi == 0) {
        if (r0 < BSZ)     atomicMax(&g_rowmax_u[r0], fenc(mx0));
        if (r0 + 8 < BSZ) atomicMax(&g_rowmax_u[r0 + 8], fenc(mx1));
    }
    if (mi < 2 && r0 < NG) {
        const int cg = n0 + tt * 8 + c0l;
        if (cg < NTOT)
            *(float2*)&g_SaaSam[(size_t)r0 * NTOT + cg] = make_float2(d2[0], d2[1]);
    }
}

// ---------------------------------------------------------------------------
// K4: fused epilogue — SAME 1-cell/thread body as R14, but 128-thread blocks
//     and 1026 of them: grid no longer caps occupancy (~7 blocks/SM).
// ---------------------------------------------------------------------------
__global__ __launch_bounds__(128, 8) void epi_kernel(const float* __restrict__ rank_mean,
                                                     float* __restrict__ out) {
    __shared__ float s_cnt[NG], s_sum[NG];
    __shared__ __align__(16) float st_glog[640];
    __shared__ __align__(16) float st_gprb[640];
    const int tid = threadIdx.x;
    if (tid < NG) { s_cnt[tid] = 0.f; s_sum[tid] = 0.f; }
    __syncthreads();

    const int idx = blockIdx.x * 128 + tid;       // grid sized exactly
    const int b = idx / NTOT;
    const int n = idx - b * NTOT;

    const float sim = g_S[(size_t)b * NTOT + n];
    float sqa[NG];
    #pragma unroll
    for (int g = 0; g < NG; g++)
        sqa[g] = g_S[(size_t)(BSZ + b * NG + g) * NTOT + n];
    float ss[10];
    #pragma unroll
    for (int i = 0; i < 10; i++)
        ss[i] = g_SaaSam[(size_t)i * NTOT + n];
    float cbg[NG], rm[NG];
    #pragma unroll
    for (int g = 0; g < NG; g++) { cbg[g] = g_Cbg[b * NG + g]; rm[g] = rank_mean[g]; }
    const float rowmax = fdec(g_rowmax_u[b]);

    float lg[NG], ev[NG];
    #pragma unroll
    for (int g = 0; g < NG; g++)
        lg[g] = cbg[g] + sqa[g] - 0.5f * ss[g] - ss[5 + g];
    float m = lg[0]; int bi = 0;
    #pragma unroll
    for (int g = 1; g < NG; g++) if (lg[g] > m) { m = lg[g]; bi = g; }

    float sum = 0.f;
    #pragma unroll
    for (int g = 0; g < NG; g++) {
        float ln = lg[g] - m;
        st_glog[tid * 5 + g] = ln;
        float e = __expf(ln);
        ev[g] = e; sum += e;
    }
    float isum = 1.f / sum;
    #pragma unroll
    for (int g = 0; g < NG; g++)
        st_gprb[tid * 5 + g] = ev[g] * isum;

    float bd = fabsf(sim - rm[0]); int cp = 0;
    #pragma unroll
    for (int g = 1; g < NG; g++) {
        float d = fabsf(sim - rm[g]);
        if (d < bd) { bd = d; cp = g; }
    }
    int cd = (int)floorf((sim + 1.0f) / 2.0f * 5.0f);

    bool golden = (n < BSZ) && (n == ((b + 8) & 15));
    bool eye    = (n == b);

    out[OFF_CLOG + idx] = sim - rowmax;
    out[OFF_ACC  + idx] = eye ? 0.f : sim;
    out[OFF_GLBL + idx] = (float)((eye || golden) ? (NG - 1) : cp);
    out[OFF_CLBL + idx] = (float)(golden ? (NG - 1) : bi);
    out[OFF_CDST + idx] = (float)cd;

    atomicAdd(&s_cnt[bi], 1.f);
    atomicAdd(&s_sum[bi], sim);
    __syncthreads();

    // coalesced vector write-out of staged glog/gprb (640 floats each)
    {
        const float4* sg = (const float4*)st_glog;
        const float4* sp = (const float4*)st_gprb;
        float4* dg = (float4*)(out + OFF_GLOG + (size_t)blockIdx.x * 640);
        float4* dp = (float4*)(out + OFF_GPRB + (size_t)blockIdx.x * 640);
        #pragma unroll
        for (int i = 0; i < 2; i++) {
            int e = tid + i * 128;
            if (e < 160) { dg[e] = sg[e]; dp[e] = sp[e]; }
        }
    }
    if (tid < NG) {
        atomicAdd(&g_cnt[tid], s_cnt[tid]);
        atomicAdd(&g_sum[tid], s_sum[tid]);
    }
}

// ---------------------------------------------------------------------------
// K5: rank-mean EMA finalize
// ---------------------------------------------------------------------------
__global__ void finish_kernel(const float* __restrict__ rank_mean,
                              float* __restrict__ out) {
    int g = threadIdx.x;
    if (g < NG) {
        float c = g_cnt[g], s = g_sum[g];
        float cur = s / (c + 1e-12f);
        float upd = (c != 0.f) ? 1.f : 0.f;
        out[OFF_NRM + g] = (1.f - upd * 0.1f) * rank_mean[g] + upd * 0.1f * cur;
    }
}

// ---------------------------------------------------------------------------
extern "C" void kernel_launch(void* const* d_in, const int* in_sizes, int n_in,
                              void* d_out, int out_size) {
    const float* sent_q    = (const float*)d_in[0];
    const float* sent_k    = (const float*)d_in[1];
    const float* queue     = (const float*)d_in[2];
    const float* mu        = (const float*)d_in[3];
    const float* lg_sigma2 = (const float*)d_in[4];
    const float* pi        = (const float*)d_in[5];
    const float* rank_mean = (const float*)d_in[6];
    float* out = (float*)d_out;

    cudaFuncSetAttribute(gemm_mma_kernel,
                         cudaFuncAttributeMaxDynamicSharedMemorySize, SMTOT);

    w2_kernel<<<(128 * HD + 255) / 256, 256>>>(sent_q, mu, lg_sigma2);
    cbg_kernel<<<10, 256>>>(sent_q, mu, lg_sigma2, pi);
    gemm_mma_kernel<<<(NTOT + 63) / 64, 512, SMTOT>>>(sent_k, queue, lg_sigma2);
    epi_kernel<<<(BSZ * NTOT) / 128, 128>>>(rank_mean, out);
    finish_kernel<<<1, 32>>>(rank_mean, out);
}

// round 17
// speedup vs baseline: 1.4443x; 1.0723x over previous
#include <cuda_runtime.h>
#include <cuda_bf16.h>
#include <math.h>
#include <stdint.h>

#define BSZ   16
#define NTOT  8208
#define HD    768
#define NG    5
#define NM    96

// output offsets (flattened concat of the 8 reference outputs, float32)
#define OFF_GLOG 0
#define OFF_GPRB 656640
#define OFF_CLOG 1313280
#define OFF_ACC  1444608
#define OFF_NRM  1575936
#define OFF_GLBL 1575941
#define OFF_CLBL 1707269
#define OFF_CDST 1838597

__device__ __nv_bfloat16 g_W2h[128 * HD];
__device__ __nv_bfloat16 g_W2l[128 * HD];
__device__ float g_Cbg[BSZ * NG];
__device__ __align__(256) float g_SaaSam[10 * NTOT];   // SoA
__device__ __align__(256) float g_S[(NM) * NTOT];
__device__ unsigned g_rowmax_u[BSZ];
__device__ float g_cnt[NG];
__device__ float g_sum[NG];
__device__ unsigned g_done;

__device__ __forceinline__ float wred(float v) {
    #pragma unroll
    for (int o = 16; o; o >>= 1) v += __shfl_down_sync(0xffffffffu, v, o);
    return v;
}
__device__ __forceinline__ unsigned fenc(float f) {
    unsigned b = __float_as_uint(f);
    return (b & 0x80000000u) ? ~b : (b | 0x80000000u);
}
__device__ __forceinline__ float fdec(unsigned u) {
    return (u & 0x80000000u) ? __uint_as_float(u ^ 0x80000000u)
                             : __uint_as_float(~u);
}

// ---------------------------------------------------------------------------
// mma.sync / ldmatrix / cp.async helpers (plain sm_80+)
// ---------------------------------------------------------------------------
__device__ __forceinline__ uint32_t smem_u32(const void* p) {
    uint32_t a;
    asm("{ .reg .u64 t; cvta.to.shared.u64 t, %1; cvt.u32.u64 %0, t; }"
        : "=r"(a) : "l"(p));
    return a;
}
__device__ __forceinline__ void mma16816(float* c, const uint32_t* a, const uint32_t* b) {
    asm volatile("mma.sync.aligned.m16n8k16.row.col.f32.bf16.bf16.f32 "
                 "{%0,%1,%2,%3}, {%4,%5,%6,%7}, {%8,%9}, {%0,%1,%2,%3};"
                 : "+f"(c[0]), "+f"(c[1]), "+f"(c[2]), "+f"(c[3])
                 : "r"(a[0]), "r"(a[1]), "r"(a[2]), "r"(a[3]),
                   "r"(b[0]), "r"(b[1]));
}
__device__ __forceinline__ void ldsm4(uint32_t* r, uint32_t addr) {
    asm volatile("ldmatrix.sync.aligned.m8n8.x4.shared.b16 {%0,%1,%2,%3}, [%4];"
                 : "=r"(r[0]), "=r"(r[1]), "=r"(r[2]), "=r"(r[3]) : "r"(addr));
}
__device__ __forceinline__ void cp16(uint32_t dst, const void* src) {
    size_t g;
    asm("cvta.to.global.u64 %0, %1;" : "=l"(g) : "l"(src));
    asm volatile("cp.async.ca.shared.global [%0], [%1], 16;"
                 :: "r"(dst), "l"(g) : "memory");
}

__device__ __forceinline__ void split2(float v0, float v1, uint32_t& h, uint32_t& l) {
    asm("cvt.rn.bf16x2.f32 %0, %1, %2;" : "=r"(h) : "f"(v1), "f"(v0));
    float h0 = __uint_as_float(h << 16);
    float h1 = __uint_as_float(h & 0xffff0000u);
    float l0 = v0 - h0, l1 = v1 - h1;
    asm("cvt.rn.bf16x2.f32 %0, %1, %2;" : "=r"(l) : "f"(l1), "f"(l0));
}
__device__ __forceinline__ void split8(const float* v, uint4& hi, uint4& lo) {
    uint32_t hs[4], ls[4];
    #pragma unroll
    for (int p = 0; p < 4; p++) split2(v[2 * p], v[2 * p + 1], hs[p], ls[p]);
    hi = make_uint4(hs[0], hs[1], hs[2], hs[3]);
    lo = make_uint4(ls[0], ls[1], ls[2], ls[3]);
}

// ---------------------------------------------------------------------------
// K1: merged prep — blocks [0,384): W2 build + init; blocks [384,394): Cbg
// ---------------------------------------------------------------------------
__global__ void prep_kernel(const float* __restrict__ q,
                            const float* __restrict__ mu,
                            const float* __restrict__ lgs,
                            const float* __restrict__ pi) {
    if (blockIdx.x < 384) {
        int i = blockIdx.x * 256 + threadIdx.x;
        if (blockIdx.x == 0 && threadIdx.x < 64) {
            if (threadIdx.x < NG)  { g_cnt[threadIdx.x] = 0.f; g_sum[threadIdx.x] = 0.f; }
            if (threadIdx.x < BSZ) g_rowmax_u[threadIdx.x] = 0u;
            if (threadIdx.x == 32) g_done = 0u;
        }
        if (i >= 128 * HD) return;
        int m = i / HD, h = i - m * HD;
        float w = 0.f;
        if (m < BSZ) w = q[m * HD + h];
        else if (m < NM) {
            int bg = m - BSZ;
            int b = bg / NG, g = bg - b * NG;
            w = q[b * HD + h] * expf(-lgs[g * HD + h]);
        } else if (m < NM + NG) {
            int g = m - NM;
            w = mu[g * HD + h] * expf(-lgs[g * HD + h]);
        }
        __nv_bfloat16 hb = __float2bfloat16(w);
        float lo = w - __bfloat162float(hb);
        g_W2h[i] = hb;
        g_W2l[i] = __float2bfloat16(lo);
    } else {
        int job = (blockIdx.x - 384) * 8 + (threadIdx.x >> 5);
        int lane = threadIdx.x & 31;
        if (job >= BSZ * NG) return;
        int b = job / NG, g = job - b * NG;

        float a1 = 0.f, a2 = 0.f;
        for (int h = lane; h < HD; h += 32) {
            float lv = lgs[g * HD + h];
            float iv = expf(-lv);
            float m_ = mu[g * HD + h];
            float mv = m_ * iv;
            float qv = q[b * HD + h];
            a1 += lv + qv * qv * iv + m_ * mv;
            a2 += qv * mv;
        }
        a1 = wred(a1); a2 = wred(a2);
        if (lane == 0) {
            float m = pi[0];
            #pragma unroll
            for (int i = 1; i < NG; i++) m = fmaxf(m, pi[i]);
            float s = 0.f;
            #pragma unroll
            for (int i = 0; i < NG; i++) s += expf(pi[i] - m);
            float lse = m + logf(s);
            const float LG2PID = 768.0f * 1.8378770351409912f;
            g_Cbg[job] = (pi[g] - lse) - 0.5f * (LG2PID + a1) + a2;
        }
    }
}

// ===========================================================================
// K2: HMMA bf16x3 fused GEMM (identical to R16, passing)
// ===========================================================================
#define NSTG  12
#define A_HI  0
#define A_LO  36864
#define B_HI  73728
#define B_LO  92160
#define SQ_HI 110592
#define SQ_LO 129024
#define IV_HI 147456
#define IV_LO 155216
#define ZROW  162976
#define SMTOT 162992

__global__ __launch_bounds__(512, 1) void gemm_mma_kernel(const float* __restrict__ sk,
                                                          const float* __restrict__ qu,
                                                          const float* __restrict__ lgs) {
    extern __shared__ __align__(1024) unsigned char smem[];
    const uint32_t sb = smem_u32(smem);
    const int tid = threadIdx.x;
    const int lane = tid & 31;
    const int warp = tid >> 5;
    const int mi = warp >> 2;
    const int ni = warp & 3;
    const int n0 = blockIdx.x * 64;

    for (int i = tid; i < 5 * 384; i += 512) {
        int r = i / 384, kp = i - r * 384;
        float2 v2 = *(const float2*)(lgs + r * HD + kp * 2);
        uint32_t h, l;
        split2(expf(-v2.x), expf(-v2.y), h, l);
        *(uint32_t*)(smem + IV_HI + r * 1552 + kp * 4) = h;
        *(uint32_t*)(smem + IV_LO + r * 1552 + kp * 4) = l;
    }
    if (tid < 4) *(uint32_t*)(smem + ZROW + tid * 4) = 0u;

    const __nv_bfloat16* aps[4];
    uint32_t apd[4];
    #pragma unroll
    for (int i = 0; i < 4; i++) {
        int j = tid + i * 512;
        int part = j >> 10;
        int rem = j & 1023;
        int row = rem >> 3, ch = rem & 7;
        aps[i] = (part ? g_W2l : g_W2h) + row * HD + ch * 8;
        apd[i] = sb + (part ? A_LO : A_HI) + row * 144 + ch * 16;
    }

    const int col = tid >> 3;
    const int kq8 = (tid & 7) * 8;
    const int n   = n0 + col;
    const bool okB = (n < NTOT);
    const float* bsrc = okB ? ((n < BSZ) ? sk + n * HD : qu + (size_t)(n - BSZ) * HD)
                            : sk;
    const uint32_t bOff = col * 144 + kq8 * 2;

    const uint32_t aB = sb + A_HI + (mi * 32 + (lane & 15)) * 144 + (lane >> 4) * 16;
    const uint32_t bBm = sb + B_HI + (ni * 16 + (lane >> 4) * 8 + (lane & 7)) * 144
                         + ((lane >> 3) & 1) * 16;
    const int rr = lane & 15;
    const uint32_t ivH = (rr < 5) ? sb + IV_HI + rr * 1552 + (lane >> 4) * 16 : sb + ZROW;
    const uint32_t ivL = (rr < 5) ? sb + IV_LO + rr * 1552 + (lane >> 4) * 16 : sb + ZROW;
    const int ivs = (rr < 5) ? 32 : 0;
    const int tt = ni * 2 + mi;
    const uint32_t sqBm = sb + SQ_HI + ((lane >> 4) ? 18432u : 0u)
                          + (tt * 8 + (lane & 7)) * 144 + ((lane >> 3) & 1) * 16;

    float acc[2][2][4];
    #pragma unroll
    for (int a = 0; a < 2; a++)
        #pragma unroll
        for (int b = 0; b < 2; b++)
            #pragma unroll
            for (int c = 0; c < 4; c++) acc[a][b][c] = 0.f;
    float d2[4] = {0.f, 0.f, 0.f, 0.f};

    const float4 z4 = make_float4(0.f, 0.f, 0.f, 0.f);

    {
        float4 b0 = okB ? *(const float4*)(bsrc + kq8)     : z4;
        float4 b1 = okB ? *(const float4*)(bsrc + kq8 + 4) : z4;
        float v[8] = {b0.x, b0.y, b0.z, b0.w, b1.x, b1.y, b1.z, b1.w};
        uint4 hi, lo;
        split8(v, hi, lo);
        *(uint4*)(smem + B_HI + bOff) = hi;
        *(uint4*)(smem + B_LO + bOff) = lo;
        #pragma unroll
        for (int i = 0; i < 8; i++) v[i] *= v[i];
        split8(v, hi, lo);
        *(uint4*)(smem + SQ_HI + bOff) = hi;
        *(uint4*)(smem + SQ_LO + bOff) = lo;
    }
    #pragma unroll
    for (int i = 0; i < 4; i++) cp16(apd[i], aps[i]);
    asm volatile("cp.async.commit_group;" ::: "memory");

    float4 pb0 = okB ? *(const float4*)(bsrc + 64 + kq8)     : z4;
    float4 pb1 = okB ? *(const float4*)(bsrc + 64 + kq8 + 4) : z4;

    for (int s = 0; s < NSTG; s++) {
        const int buf = s & 1;
        asm volatile("cp.async.wait_group 0;" ::: "memory");
        __syncthreads();

        if (s + 1 < NSTG) {
            const int nb = buf ^ 1;
            #pragma unroll
            for (int i = 0; i < 4; i++)
                cp16(apd[i] + nb * 18432, aps[i] + (s + 1) * 64);
            asm volatile("cp.async.commit_group;" ::: "memory");
            {
                float v[8] = {pb0.x, pb0.y, pb0.z, pb0.w, pb1.x, pb1.y, pb1.z, pb1.w};
                uint4 hi, lo;
                split8(v, hi, lo);
                uint32_t off = nb * 9216 + bOff;
                *(uint4*)(smem + B_HI + off) = hi;
                *(uint4*)(smem + B_LO + off) = lo;
                #pragma unroll
                for (int i = 0; i < 8; i++) v[i] *= v[i];
                split8(v, hi, lo);
                *(uint4*)(smem + SQ_HI + off) = hi;
                *(uint4*)(smem + SQ_LO + off) = lo;
            }
            if (s + 2 < NSTG) {
                pb0 = okB ? *(const float4*)(bsrc + (s + 2) * 64 + kq8)     : z4;
                pb1 = okB ? *(const float4*)(bsrc + (s + 2) * 64 + kq8 + 4) : z4;
            }
        }

        const uint32_t aO = buf * 18432u;
        const uint32_t bO = buf * 9216u;

        uint32_t ah[2][2][4], al[2][2][4], bh[2][4], bl[2][4];
        #pragma unroll
        for (int mt = 0; mt < 2; mt++) {
            ldsm4(ah[0][mt], aB + aO + mt * 2304);
            ldsm4(al[0][mt], aB + aO + mt * 2304 + 36864);
        }
        ldsm4(bh[0], bBm + bO);
        ldsm4(bl[0], bBm + bO + 18432);

        #pragma unroll
        for (int su = 0; su < 4; su++) {
            const int cur = su & 1, nxt = cur ^ 1;
            if (su < 3) {
                const uint32_t ko = (su + 1) * 32;
                #pragma unroll
                for (int mt = 0; mt < 2; mt++) {
                    ldsm4(ah[nxt][mt], aB + aO + mt * 2304 + ko);
                    ldsm4(al[nxt][mt], aB + aO + mt * 2304 + ko + 36864);
                }
                ldsm4(bh[nxt], bBm + bO + ko);
                ldsm4(bl[nxt], bBm + bO + ko + 18432);
            }
            #pragma unroll
            for (int mt = 0; mt < 2; mt++)
                #pragma unroll
                for (int nt = 0; nt < 2; nt++) {
                    mma16816(acc[mt][nt], ah[cur][mt], &bh[cur][nt * 2]);
                    mma16816(acc[mt][nt], ah[cur][mt], &bl[cur][nt * 2]);
                    mma16816(acc[mt][nt], al[cur][mt], &bh[cur][nt * 2]);
                }
            if (mi < 2) {
                const int t16 = s * 4 + su;
                uint32_t ivh[4], ivl[4], sv[4];
                ldsm4(ivh, ivH + t16 * ivs);
                ldsm4(ivl, ivL + t16 * ivs);
                ldsm4(sv, sqBm + bO + su * 32);
                mma16816(d2, ivh, &sv[0]);
                mma16816(d2, ivh, &sv[2]);
                mma16816(d2, ivl, &sv[0]);
            }
        }
    }

    // ---- epilogue ----
    const int r0  = lane >> 2;
    const int c0l = (lane & 3) * 2;
    float mx0 = -3.4e38f, mx1 = -3.4e38f;

    #pragma unroll
    for (int mt = 0; mt < 2; mt++) {
        const int mb = mi * 32 + mt * 16;
        #pragma unroll
        for (int nt = 0; nt < 2; nt++) {
            const int cg = n0 + ni * 16 + nt * 8 + c0l;
            if (cg >= NTOT) continue;
            const float* c = acc[mt][nt];
            const int m0 = mb + r0, m1 = m0 + 8;
            if (m0 < NM) {
                *(float2*)&g_S[(size_t)m0 * NTOT + cg] = make_float2(c[0], c[1]);
                if (m0 < BSZ) mx0 = fmaxf(mx0, fmaxf(c[0], c[1]));
            } else if (m0 < NM + NG) {
                *(float2*)&g_SaaSam[(size_t)(5 + m0 - NM) * NTOT + cg] =
                    make_float2(c[0], c[1]);
            }
            if (m1 < NM) {
                *(float2*)&g_S[(size_t)m1 * NTOT + cg] = make_float2(c[2], c[3]);
                if (m1 < BSZ) mx1 = fmaxf(mx1, fmaxf(c[2], c[3]));
            } else if (m1 < NM + NG) {
                *(float2*)&g_SaaSam[(size_t)(5 + m1 - NM) * NTOT + cg] =
                    make_float2(c[2], c[3]);
            }
        }
    }
    if (mi == 0) {
        if (r0 < BSZ)     atomicMax(&g_rowmax_u[r0], fenc(mx0));
        if (r0 + 8 < BSZ) atomicMax(&g_rowmax_u[r0 + 8], fenc(mx1));
    }
    if (mi < 2 && r0 < NG) {
        const int cg = n0 + tt * 8 + c0l;
        if (cg < NTOT)
            *(float2*)&g_SaaSam[(size_t)r0 * NTOT + cg] = make_float2(d2[0], d2[1]);
    }
}

// ---------------------------------------------------------------------------
// K3: fused epilogue (R16 shape) + last-block rank-mean finalize
// ---------------------------------------------------------------------------
#define EPI_BLOCKS ((BSZ * NTOT) / 128)
__global__ __launch_bounds__(128, 8) void epi_kernel(const float* __restrict__ rank_mean,
                                                     float* __restrict__ out) {
    __shared__ float s_cnt[NG], s_sum[NG];
    __shared__ __align__(16) float st_glog[640];
    __shared__ __align__(16) float st_gprb[640];
    __shared__ unsigned s_last;
    const int tid = threadIdx.x;
    if (tid < NG) { s_cnt[tid] = 0.f; s_sum[tid] = 0.f; }
    __syncthreads();

    const int idx = blockIdx.x * 128 + tid;       // grid sized exactly
    const int b = idx / NTOT;
    const int n = idx - b * NTOT;

    const float sim = g_S[(size_t)b * NTOT + n];
    float sqa[NG];
    #pragma unroll
    for (int g = 0; g < NG; g++)
        sqa[g] = g_S[(size_t)(BSZ + b * NG + g) * NTOT + n];
    float ss[10];
    #pragma unroll
    for (int i = 0; i < 10; i++)
        ss[i] = g_SaaSam[(size_t)i * NTOT + n];
    float cbg[NG], rm[NG];
    #pragma unroll
    for (int g = 0; g < NG; g++) { cbg[g] = g_Cbg[b * NG + g]; rm[g] = rank_mean[g]; }
    const float rowmax = fdec(g_rowmax_u[b]);

    float lg[NG], ev[NG];
    #pragma unroll
    for (int g = 0; g < NG; g++)
        lg[g] = cbg[g] + sqa[g] - 0.5f * ss[g] - ss[5 + g];
    float m = lg[0]; int bi = 0;
    #pragma unroll
    for (int g = 1; g < NG; g++) if (lg[g] > m) { m = lg[g]; bi = g; }

    float sum = 0.f;
    #pragma unroll
    for (int g = 0; g < NG; g++) {
        float ln = lg[g] - m;
        st_glog[tid * 5 + g] = ln;
        float e = __expf(ln);
        ev[g] = e; sum += e;
    }
    float isum = 1.f / sum;
    #pragma unroll
    for (int g = 0; g < NG; g++)
        st_gprb[tid * 5 + g] = ev[g] * isum;

    float bd = fabsf(sim - rm[0]); int cp = 0;
    #pragma unroll
    for (int g = 1; g < NG; g++) {
        float d = fabsf(sim - rm[g]);
        if (d < bd) { bd = d; cp = g; }
    }
    int cd = (int)floorf((sim + 1.0f) / 2.0f * 5.0f);

    bool golden = (n < BSZ) && (n == ((b + 8) & 15));
    bool eye    = (n == b);

    out[OFF_CLOG + idx] = sim - rowmax;
    out[OFF_ACC  + idx] = eye ? 0.f : sim;
    out[OFF_GLBL + idx] = (float)((eye || golden) ? (NG - 1) : cp);
    out[OFF_CLBL + idx] = (float)(golden ? (NG - 1) : bi);
    out[OFF_CDST + idx] = (float)cd;

    atomicAdd(&s_cnt[bi], 1.f);
    atomicAdd(&s_sum[bi], sim);
    __syncthreads();

    // coalesced vector write-out of staged glog/gprb (640 floats each)
    {
        const float4* sg = (const float4*)st_glog;
        const float4* sp = (const float4*)st_gprb;
        float4* dg = (float4*)(out + OFF_GLOG + (size_t)blockIdx.x * 640);
        float4* dp = (float4*)(out + OFF_GPRB + (size_t)blockIdx.x * 640);
        #pragma unroll
        for (int i = 0; i < 2; i++) {
            int e = tid + i * 128;
            if (e < 160) { dg[e] = sg[e]; dp[e] = sp[e]; }
        }
    }
    if (tid < NG) {
        atomicAdd(&g_cnt[tid], s_cnt[tid]);
        atomicAdd(&g_sum[tid], s_sum[tid]);
    }

    // ---- last block computes the rank-mean EMA ----
    __threadfence();
    __syncthreads();
    if (tid == 0) {
        unsigned t = atomicAdd(&g_done, 1u);
        s_last = (t == EPI_BLOCKS - 1) ? 1u : 0u;
    }
    __syncthreads();
    if (s_last && tid < NG) {
        float c = g_cnt[tid], s = g_sum[tid];
        float cur = s / (c + 1e-12f);
        float upd = (c != 0.f) ? 1.f : 0.f;
        out[OFF_NRM + tid] = (1.f - upd * 0.1f) * rm[tid] + upd * 0.1f * cur;
    }
}

// ---------------------------------------------------------------------------
extern "C" void kernel_launch(void* const* d_in, const int* in_sizes, int n_in,
                              void* d_out, int out_size) {
    const float* sent_q    = (const float*)d_in[0];
    const float* sent_k    = (const float*)d_in[1];
    const float* queue     = (const float*)d_in[2];
    const float* mu        = (const float*)d_in[3];
    const float* lg_sigma2 = (const float*)d_in[4];
    const float* pi        = (const float*)d_in[5];
    const float* rank_mean = (const float*)d_in[6];
    float* out = (float*)d_out;

    cudaFuncSetAttribute(gemm_mma_kernel,
                         cudaFuncAttributeMaxDynamicSharedMemorySize, SMTOT);

    prep_kernel<<<394, 256>>>(sent_q, mu, lg_sigma2, pi);
    gemm_mma_kernel<<<(NTOT + 63) / 64, 512, SMTOT>>>(sent_k, queue, lg_sigma2);
    epi_kernel<<<EPI_BLOCKS, 128>>>(rank_mean, out);
}